// round 3
// baseline (speedup 1.0000x reference)
#include <cuda_runtime.h>

// Problem constants
#define NN   8192
#define FF   64
#define TWOF 128
#define RM   64          // rows per CTA
#define KT   64          // k-tile
#define NTILES (NN / KT) // 128
#define SA   68          // smem stride for A-transposed / phase-2 tiles (floats, 16B-aligned rows)
#define SB   80          // smem stride for B tile (floats, conflict-free STS.128 phases)

__global__ __launch_bounds__(256, 1)
void sage_fused_kernel(const float* __restrict__ adj,
                       const float* __restrict__ feat,
                       const float* __restrict__ W,
                       float* __restrict__ out)
{
    // Phase 1: As = A-tile transposed [k][r] (stride SA); Bs = B-tile [k][c] (stride SB)
    // Phase 2: As reused as neigh/features [r][c] (stride SA); Bs reused as W-transposed [f][o] (stride SA)
    __shared__ float As[KT * SA];      // 17408 B
    __shared__ float Bs[KT * SB];      // 20480 B
    __shared__ float rs_red[RM * 4];   // 1024 B   (total ~38.9 KB)

    const int tid  = threadIdx.x;
    const int tx   = tid & 15;         // 16 col-groups of 4
    const int ty   = tid >> 4;         // 16 row-groups of 4
    const int lrow = tid >> 2;         // loader row within tile (0..63)
    const int lq   = (tid & 3) << 2;   // loader col base (0,4,8,12)
    const int row0 = blockIdx.x * RM;

    float acc[4][4];
    #pragma unroll
    for (int i = 0; i < 4; i++)
        #pragma unroll
        for (int j = 0; j < 4; j++) acc[i][j] = 0.0f;
    float rsum = 0.0f;

    const float* aRow = adj + (size_t)(row0 + lrow) * NN + lq;

    float4 ra[4], rb[4];
    // Prologue: stage tile 0 into registers
    {
        const float* ap = aRow;
        const float* bp = feat + (size_t)lrow * FF + lq;
        #pragma unroll
        for (int p = 0; p < 4; p++) {
            ra[p] = *(const float4*)(ap + 16 * p);
            rb[p] = *(const float4*)(bp + 16 * p);
        }
    }

    for (int t = 0; t < NTILES; t++) {
        // Store staged tile to smem; accumulate rowsum from the A registers
        #pragma unroll
        for (int p = 0; p < 4; p++) {
            const int c = lq + 16 * p;
            As[(c + 0) * SA + lrow] = ra[p].x;
            As[(c + 1) * SA + lrow] = ra[p].y;
            As[(c + 2) * SA + lrow] = ra[p].z;
            As[(c + 3) * SA + lrow] = ra[p].w;
            rsum += (ra[p].x + ra[p].y) + (ra[p].z + ra[p].w);
            *(float4*)&Bs[lrow * SB + c] = rb[p];
        }
        __syncthreads();

        // Prefetch next tile into registers (overlaps with compute below)
        if (t + 1 < NTILES) {
            const float* ap = aRow + (size_t)(t + 1) * KT;
            const float* bp = feat + (size_t)((t + 1) * KT + lrow) * FF + lq;
            #pragma unroll
            for (int p = 0; p < 4; p++) {
                ra[p] = *(const float4*)(ap + 16 * p);
                rb[p] = *(const float4*)(bp + 16 * p);
            }
        }

        // 4x4 register-blocked FMA over the k-tile
        #pragma unroll 16
        for (int kk = 0; kk < KT; kk++) {
            float4 av = *(const float4*)&As[kk * SA + ty * 4];
            float4 bv = *(const float4*)&Bs[kk * SB + tx * 4];
            float a[4] = {av.x, av.y, av.z, av.w};
            float b[4] = {bv.x, bv.y, bv.z, bv.w};
            #pragma unroll
            for (int i = 0; i < 4; i++)
                #pragma unroll
                for (int j = 0; j < 4; j++)
                    acc[i][j] = fmaf(a[i], b[j], acc[i][j]);
        }
        __syncthreads();
    }

    // ---- rowsum reduction: 4 loader partials per row ----
    rs_red[lrow * 4 + (tid & 3)] = rsum;
    __syncthreads();

    float invdeg[4];
    #pragma unroll
    for (int i = 0; i < 4; i++) {
        const int r = ty * 4 + i;
        float d = rs_red[r * 4 + 0] + rs_red[r * 4 + 1] +
                  rs_red[r * 4 + 2] + rs_red[r * 4 + 3] + 1.0f;
        invdeg[i] = 1.0f / d;
    }

    // ---- Phase 2, pass A: neigh (scaled) @ W2^T ----
    // neigh into As[r][c] (stride SA); W2 transposed into Bs[f][o] (stride SA)
    #pragma unroll
    for (int i = 0; i < 4; i++) {
        #pragma unroll
        for (int j = 0; j < 4; j++)
            As[(ty * 4 + i) * SA + tx * 4 + j] = acc[i][j] * invdeg[i];
    }
    {
        const int o = tid >> 2;
        #pragma unroll
        for (int p = 0; p < 4; p++) {
            const int f = lq + 16 * p;
            float4 w = *(const float4*)(W + (size_t)o * TWOF + FF + f);  // W2 = W[:, 64:128]
            Bs[(f + 0) * SA + o] = w.x;
            Bs[(f + 1) * SA + o] = w.y;
            Bs[(f + 2) * SA + o] = w.z;
            Bs[(f + 3) * SA + o] = w.w;
        }
    }
    __syncthreads();

    float acc2[4][4];
    #pragma unroll
    for (int i = 0; i < 4; i++)
        #pragma unroll
        for (int j = 0; j < 4; j++) acc2[i][j] = 0.0f;

    #pragma unroll 8
    for (int kk = 0; kk < FF; kk++) {
        float a0 = As[(ty * 4 + 0) * SA + kk];
        float a1 = As[(ty * 4 + 1) * SA + kk];
        float a2 = As[(ty * 4 + 2) * SA + kk];
        float a3 = As[(ty * 4 + 3) * SA + kk];
        float4 bv = *(const float4*)&Bs[kk * SA + tx * 4];
        float b[4] = {bv.x, bv.y, bv.z, bv.w};
        float a[4] = {a0, a1, a2, a3};
        #pragma unroll
        for (int i = 0; i < 4; i++)
            #pragma unroll
            for (int j = 0; j < 4; j++)
                acc2[i][j] = fmaf(a[i], b[j], acc2[i][j]);
    }
    __syncthreads();

    // ---- Phase 2, pass B: features @ W1^T ----
    {
        const float* fp = feat + (size_t)(row0 + lrow) * FF + lq;
        #pragma unroll
        for (int p = 0; p < 4; p++)
            *(float4*)&As[lrow * SA + lq + 16 * p] = *(const float4*)(fp + 16 * p);

        const int o = tid >> 2;
        #pragma unroll
        for (int p = 0; p < 4; p++) {
            const int f = lq + 16 * p;
            float4 w = *(const float4*)(W + (size_t)o * TWOF + f);       // W1 = W[:, 0:64]
            Bs[(f + 0) * SA + o] = w.x;
            Bs[(f + 1) * SA + o] = w.y;
            Bs[(f + 2) * SA + o] = w.z;
            Bs[(f + 3) * SA + o] = w.w;
        }
    }
    __syncthreads();

    #pragma unroll 8
    for (int kk = 0; kk < FF; kk++) {
        float a0 = As[(ty * 4 + 0) * SA + kk];
        float a1 = As[(ty * 4 + 1) * SA + kk];
        float a2 = As[(ty * 4 + 2) * SA + kk];
        float a3 = As[(ty * 4 + 3) * SA + kk];
        float4 bv = *(const float4*)&Bs[kk * SA + tx * 4];
        float b[4] = {bv.x, bv.y, bv.z, bv.w};
        float a[4] = {a0, a1, a2, a3};
        #pragma unroll
        for (int i = 0; i < 4; i++)
            #pragma unroll
            for (int j = 0; j < 4; j++)
                acc2[i][j] = fmaf(a[i], b[j], acc2[i][j]);
    }

    // ---- write output ----
    #pragma unroll
    for (int i = 0; i < 4; i++) {
        float4 o4 = make_float4(acc2[i][0], acc2[i][1], acc2[i][2], acc2[i][3]);
        *(float4*)(out + (size_t)(row0 + ty * 4 + i) * FF + tx * 4) = o4;
    }
}

extern "C" void kernel_launch(void* const* d_in, const int* in_sizes, int n_in,
                              void* d_out, int out_size)
{
    const float* adj  = (const float*)d_in[0];   // [8192, 8192]
    const float* feat = (const float*)d_in[1];   // [8192, 64]
    const float* W    = (const float*)d_in[2];   // [64, 128]
    float* out        = (float*)d_out;           // [8192, 64]

    sage_fused_kernel<<<NN / RM, 256>>>(adj, feat, W, out);
}

// round 6
// speedup vs baseline: 1.5083x; 1.5083x over previous
#include <cuda_runtime.h>
#include <cstdint>

#define NN 8192
#define FF 64
#define RM 64
#define KT 64
#define NT (NN / KT)
#define SA 68   // smem row stride (floats); mult of 4 for 16B ldmatrix alignment

// feat transposed to [n][k], tf32-rounded bit patterns
__device__ uint32_t g_featT[FF * NN];

static __device__ __forceinline__ uint32_t tf32b(float x) {
    uint32_t r; asm("cvt.rna.tf32.f32 %0, %1;" : "=r"(r) : "f"(x)); return r;
}
static __device__ __forceinline__ uint32_t s2u(const void* p) {
    uint32_t a;
    asm("{ .reg .u64 t; cvta.to.shared.u64 t, %1; cvt.u32.u64 %0, t; }" : "=r"(a) : "l"(p));
    return a;
}
static __device__ __forceinline__ void ldsm4(uint32_t& a0, uint32_t& a1,
                                             uint32_t& a2, uint32_t& a3, uint32_t addr) {
    asm volatile("ldmatrix.sync.aligned.m8n8.x4.shared.b16 {%0,%1,%2,%3}, [%4];"
                 : "=r"(a0), "=r"(a1), "=r"(a2), "=r"(a3) : "r"(addr));
}
static __device__ __forceinline__ void mma_tf32(float* c, uint32_t a0, uint32_t a1,
                                                uint32_t a2, uint32_t a3,
                                                uint32_t b0, uint32_t b1) {
    asm volatile(
        "mma.sync.aligned.m16n8k8.row.col.f32.tf32.tf32.f32 "
        "{%0,%1,%2,%3}, {%4,%5,%6,%7}, {%8,%9}, {%0,%1,%2,%3};"
        : "+f"(c[0]), "+f"(c[1]), "+f"(c[2]), "+f"(c[3])
        : "r"(a0), "r"(a1), "r"(a2), "r"(a3), "r"(b0), "r"(b1));
}

// ---- prep: featT[n][k] = tf32(feat[k][n]) via smem tile transpose ----
__global__ __launch_bounds__(256)
void prep_featT(const float* __restrict__ feat)
{
    __shared__ float t[64][65];
    const int k0 = blockIdx.x * 64;
    const int tid = threadIdx.x;
    const int r = tid >> 2, q = tid & 3;

    const float* fp = feat + (size_t)(k0 + r) * FF + 16 * q;   // row = k, cols = n
    #pragma unroll
    for (int j = 0; j < 4; j++) {
        float4 v = *(const float4*)(fp + 4 * j);
        t[r][16 * q + 4 * j + 0] = v.x;
        t[r][16 * q + 4 * j + 1] = v.y;
        t[r][16 * q + 4 * j + 2] = v.z;
        t[r][16 * q + 4 * j + 3] = v.w;
    }
    __syncthreads();

    // now r = n, write k chunk [k0+16q, k0+16q+16)
    uint32_t* dst = g_featT + (size_t)r * NN + k0 + 16 * q;
    #pragma unroll
    for (int j = 0; j < 4; j++) {
        uint4 c;
        c.x = tf32b(t[16 * q + 4 * j + 0][r]);
        c.y = tf32b(t[16 * q + 4 * j + 1][r]);
        c.z = tf32b(t[16 * q + 4 * j + 2][r]);
        c.w = tf32b(t[16 * q + 4 * j + 3][r]);
        *(uint4*)(dst + 4 * j) = c;
    }
}

// ---- main fused kernel ----
__global__ __launch_bounds__(256, 1)
void sage_mma_kernel(const float* __restrict__ adj,
                     const float* __restrict__ feat,
                     const float* __restrict__ W,
                     float* __restrict__ out)
{
    extern __shared__ float sm[];
    float* As = sm;                 // 64 x SA   (A tile, tf32 bits as float slots)
    float* Bs = As + 64 * SA;       // 64 x SA   (B tile, n-major)
    float* rs = Bs + 64 * SA;       // 256 rowsum partials
    float* Ws = rs + 256;           // 128 x SA  (W transposed: WsT[k][o])

    const int tid = threadIdx.x;
    const int lane = tid & 31, warp = tid >> 5;
    const int wm = warp >> 1, wn = warp & 1;    // warp tile: rows 16*wm, cols 32*wn
    const int row0 = blockIdx.x * RM;
    const int r = tid >> 2, q = tid & 3;        // loader mapping

    const float* aP = adj + (size_t)(row0 + r) * NN + 16 * q;
    const uint32_t* bP = g_featT + (size_t)r * NN + 16 * q;   // r = n here

    float acc[4][4] = {};
    float rsum = 0.0f;

    float4 ra[4]; uint4 rb[4];
    #pragma unroll
    for (int j = 0; j < 4; j++) {
        ra[j] = *(const float4*)(aP + 4 * j);
        rb[j] = *(const uint4*)(bP + 4 * j);
    }

    // ldmatrix per-lane addresses (matrices: 0=r0-7/k0-3, 1=r8-15/k0-3(A) or r0-7/k4-7(B)...)
    const int mi = lane >> 3, ri = lane & 7;
    const uint32_t aAddr  = s2u(&As[(16 * wm + (mi & 1) * 8 + ri) * SA + (mi >> 1) * 4]);
    const uint32_t bAddr0 = s2u(&Bs[(32 * wn + (mi >> 1) * 8 + ri) * SA + (mi & 1) * 4]);
    const uint32_t bAddr1 = s2u(&Bs[(32 * wn + 16 + (mi >> 1) * 8 + ri) * SA + (mi & 1) * 4]);

    for (int t = 0; t < NT; t++) {
        // stage current tile to smem (rowsum from raw fp32; A rounded to tf32)
        #pragma unroll
        for (int j = 0; j < 4; j++) {
            float4 v = ra[j];
            rsum += (v.x + v.y) + (v.z + v.w);
            uint4 c;
            c.x = tf32b(v.x); c.y = tf32b(v.y); c.z = tf32b(v.z); c.w = tf32b(v.w);
            *(uint4*)&As[r * SA + 16 * q + 4 * j] = c;
            *(uint4*)&Bs[r * SA + 16 * q + 4 * j] = rb[j];
        }
        __syncthreads();

        // prefetch next tile into registers (overlaps the MMAs below)
        if (t + 1 < NT) {
            const float*    ap = aP + (size_t)(t + 1) * KT;
            const uint32_t* bp = bP + (t + 1) * KT;
            #pragma unroll
            for (int j = 0; j < 4; j++) {
                ra[j] = *(const float4*)(ap + 4 * j);
                rb[j] = *(const uint4*)(bp + 4 * j);
            }
        }

        // 8 k-steps of m16n8k8 over the 64-k tile
        #pragma unroll
        for (int ks = 0; ks < 8; ks++) {
            uint32_t a0, a1, a2, a3, b0, b1, b2, b3, b4, b5, b6, b7;
            ldsm4(a0, a1, a2, a3, aAddr  + ks * 32);
            ldsm4(b0, b1, b2, b3, bAddr0 + ks * 32);
            ldsm4(b4, b5, b6, b7, bAddr1 + ks * 32);
            mma_tf32(acc[0], a0, a1, a2, a3, b0, b1);
            mma_tf32(acc[1], a0, a1, a2, a3, b2, b3);
            mma_tf32(acc[2], a0, a1, a2, a3, b4, b5);
            mma_tf32(acc[3], a0, a1, a2, a3, b6, b7);
        }
        __syncthreads();
    }

    // ---- rowsum reduce ----
    rs[tid] = rsum;
    __syncthreads();

    // ---- neigh (scaled by 1/deg) into As; feat fp32 into Bs; W^T into Ws ----
    {
        const int g = lane >> 2, t2 = lane & 3;
        const int rowa = 16 * wm + g, rowb = rowa + 8;
        float inva = 1.0f / (rs[4 * rowa] + rs[4 * rowa + 1] +
                             rs[4 * rowa + 2] + rs[4 * rowa + 3] + 1.0f);
        float invb = 1.0f / (rs[4 * rowb] + rs[4 * rowb + 1] +
                             rs[4 * rowb + 2] + rs[4 * rowb + 3] + 1.0f);
        #pragma unroll
        for (int nb = 0; nb < 4; nb++) {
            const int col = 32 * wn + 8 * nb + 2 * t2;
            As[rowa * SA + col]     = acc[nb][0] * inva;
            As[rowa * SA + col + 1] = acc[nb][1] * inva;
            As[rowb * SA + col]     = acc[nb][2] * invb;
            As[rowb * SA + col + 1] = acc[nb][3] * invb;
        }
    }
    {
        const float* fp = feat + (size_t)(row0 + r) * FF + 16 * q;
        #pragma unroll
        for (int j = 0; j < 4; j++)
            *(float4*)&Bs[r * SA + 16 * q + 4 * j] = *(const float4*)(fp + 4 * j);

        const float* wp = W + (size_t)r * 128 + 32 * q;   // r = output o here
        #pragma unroll
        for (int j = 0; j < 32; j++)
            Ws[(32 * q + j) * SA + r] = wp[j];            // WsT[k][o]
    }
    __syncthreads();

    // ---- exact fp32 epilogue GEMM: out[r][o] = feat.W1^T + neigh.W2^T ----
    float acc2[16] = {};
    #pragma unroll 4
    for (int k = 0; k < 64; k++) {
        float af = Bs[r * SA + k];
        float an = As[r * SA + k];
        #pragma unroll
        for (int j = 0; j < 4; j++) {
            float4 w1 = *(float4*)&Ws[k * SA + 16 * q + 4 * j];
            float4 w2 = *(float4*)&Ws[(64 + k) * SA + 16 * q + 4 * j];
            acc2[4 * j + 0] = fmaf(af, w1.x, fmaf(an, w2.x, acc2[4 * j + 0]));
            acc2[4 * j + 1] = fmaf(af, w1.y, fmaf(an, w2.y, acc2[4 * j + 1]));
            acc2[4 * j + 2] = fmaf(af, w1.z, fmaf(an, w2.z, acc2[4 * j + 2]));
            acc2[4 * j + 3] = fmaf(af, w1.w, fmaf(an, w2.w, acc2[4 * j + 3]));
        }
    }

    float* op = out + (size_t)(row0 + r) * FF + 16 * q;
    #pragma unroll
    for (int j = 0; j < 4; j++) {
        float4 v = make_float4(acc2[4 * j + 0], acc2[4 * j + 1],
                               acc2[4 * j + 2], acc2[4 * j + 3]);
        *(float4*)(op + 4 * j) = v;
    }
}

#define SMEM_BYTES ((64 * SA + 64 * SA + 256 + 128 * SA) * 4)

extern "C" void kernel_launch(void* const* d_in, const int* in_sizes, int n_in,
                              void* d_out, int out_size)
{
    const float* adj  = (const float*)d_in[0];   // [8192, 8192]
    const float* feat = (const float*)d_in[1];   // [8192, 64]
    const float* W    = (const float*)d_in[2];   // [64, 128]
    float* out        = (float*)d_out;           // [8192, 64]

    cudaFuncSetAttribute(sage_mma_kernel,
                         cudaFuncAttributeMaxDynamicSharedMemorySize, SMEM_BYTES);
    prep_featT<<<NN / 64, 256>>>(feat);
    sage_mma_kernel<<<NN / RM, 256, SMEM_BYTES>>>(adj, feat, W, out);
}